// round 1
// baseline (speedup 1.0000x reference)
#include <cuda_runtime.h>

#define BATCH    8
#define TLEN     16384
#define CH       32
#define NB       6
#define NTHREADS 576
#define HALO     63
#define T_TILE   (NTHREADS - 2*HALO)              /* 450 */
#define NTILES   ((TLEN + T_TILE - 1) / T_TILE)   /* 37  */
#define HBSTRIDE 33
#define HB_FLOATS (NTHREADS * HBSTRIDE)           /* 19008 */
#define NWARPS   (NTHREADS / 32)                  /* 18 */
#define W_FLOATS (3*CH*CH + 3*CH*CH + CH*CH + 3*CH)  /* 7264 */
#define SMEM_FLOATS (HB_FLOATS + W_FLOATS + 2*NWARPS)
#define SMEM_BYTES  (SMEM_FLOATS * 4)

__device__ float g_partials[BATCH * NTILES * 2];

__device__ __forceinline__ float sigm_(float x) {
    return 1.0f / (1.0f + __expf(-x));
}
__device__ __forceinline__ float tanh_(float x) {
    float e = __expf(2.0f * x);
    return 1.0f - 2.0f / (e + 1.0f);
}
__device__ __forceinline__ void fma4(float* acc, float4 w, float v) {
    acc[0] = fmaf(w.x, v, acc[0]);
    acc[1] = fmaf(w.y, v, acc[1]);
    acc[2] = fmaf(w.z, v, acc[2]);
    acc[3] = fmaf(w.w, v, acc[3]);
}

__global__ void __launch_bounds__(NTHREADS, 1)
wavenet_kernel(const float* __restrict__ x,
               const float* __restrict__ w_init,  const float* __restrict__ b_init,
               const float* __restrict__ w_tanh,  const float* __restrict__ b_tanh,
               const float* __restrict__ w_sig,   const float* __restrict__ b_sig,
               const float* __restrict__ w_skip,  const float* __restrict__ b_skip,
               const float* __restrict__ w_final, const float* __restrict__ b_final,
               const float* __restrict__ w_dense)
{
    extern __shared__ float smem[];
    float* hb   = smem;                    // [NTHREADS][33]
    float* swt  = smem + HB_FLOATS;        // 3*32*32
    float* sws  = swt + 3*CH*CH;           // 3*32*32
    float* swk  = sws + 3*CH*CH;           // 32*32
    float* sbt  = swk + CH*CH;             // 32
    float* sbs  = sbt + CH;                // 32
    float* sbk  = sbs + CH;                // 32
    float* sred = sbk + CH;                // 2*NWARPS

    const int tid  = threadIdx.x;
    const int bidx = blockIdx.x;
    const int b    = bidx / NTILES;
    const int tile = bidx - b * NTILES;
    const int t0   = tile * T_TILE;
    const int tg   = t0 - HALO + tid;
    const bool in_seq = (tg >= 0) && (tg < TLEN);

    const float xv = in_seq ? x[(size_t)b * TLEN + tg] : 0.0f;

    // ---- initial 1x1 conv: h = relu(x * w_init + b_init), zero outside sequence ----
    #pragma unroll
    for (int c = 0; c < CH; ++c) {
        float h = in_seq ? fmaxf(fmaf(xv, __ldg(&w_init[c]), __ldg(&b_init[c])), 0.0f) : 0.0f;
        hb[tid * HBSTRIDE + c] = h;
    }

    float at[CH], ag[CH];

    // ---- 6 residual blocks, all in shared memory ----
    for (int blk = 0; blk < NB; ++blk) {
        // cooperative weight load for this block
        {
            const float4* g = (const float4*)(w_tanh + blk * 3*CH*CH);
            float4* s = (float4*)swt;
            for (int j = tid; j < 768; j += NTHREADS) s[j] = g[j];
            g = (const float4*)(w_sig + blk * 3*CH*CH);
            s = (float4*)sws;
            for (int j = tid; j < 768; j += NTHREADS) s[j] = g[j];
            g = (const float4*)(w_skip + blk * CH*CH);
            s = (float4*)swk;
            for (int j = tid; j < 256; j += NTHREADS) s[j] = g[j];
            if (tid < CH) {
                sbt[tid] = b_tanh[blk*CH + tid];
                sbs[tid] = b_sig [blk*CH + tid];
                sbk[tid] = b_skip[blk*CH + tid];
            }
        }
        __syncthreads();   // weights ready + hb writes from prev iter visible

        const int d = 1 << blk;
        int pm = tid - d; if (pm < 0) pm = 0;
        int pp = tid + d; if (pp > NTHREADS - 1) pp = NTHREADS - 1;

        const float* hrm = hb + pm  * HBSTRIDE;
        const float* hr0 = hb + tid * HBSTRIDE;
        const float* hrp = hb + pp  * HBSTRIDE;

        #pragma unroll
        for (int c = 0; c < CH; ++c) { at[c] = sbt[c]; ag[c] = sbs[c]; }

        // dilated 3-tap convs (tanh branch + sigmoid branch)
        #pragma unroll 1
        for (int ci = 0; ci < CH; ++ci) {
            const float hm = hrm[ci], h0 = hr0[ci], hp = hrp[ci];
            const float4* wt0 = (const float4*)(swt +         ci*CH);
            const float4* wt1 = (const float4*)(swt + 1024 +  ci*CH);
            const float4* wt2 = (const float4*)(swt + 2048 +  ci*CH);
            const float4* vs0 = (const float4*)(sws +         ci*CH);
            const float4* vs1 = (const float4*)(sws + 1024 +  ci*CH);
            const float4* vs2 = (const float4*)(sws + 2048 +  ci*CH);
            #pragma unroll
            for (int q = 0; q < 8; ++q) {
                fma4(at + 4*q, wt0[q], hm);
                fma4(at + 4*q, wt1[q], h0);
                fma4(at + 4*q, wt2[q], hp);
                fma4(ag + 4*q, vs0[q], hm);
                fma4(ag + 4*q, vs1[q], h0);
                fma4(ag + 4*q, vs2[q], hp);
            }
        }

        // gated activation -> small local array (dynamic-indexed below)
        float gated[CH];
        #pragma unroll
        for (int c = 0; c < CH; ++c) gated[c] = tanh_(at[c]) * sigm_(ag[c]);

        // 1x1 skip conv
        #pragma unroll
        for (int c = 0; c < CH; ++c) ag[c] = sbk[c];
        #pragma unroll 1
        for (int ci = 0; ci < CH; ++ci) {
            const float g = gated[ci];
            const float4* wk = (const float4*)(swk + ci*CH);
            #pragma unroll
            for (int q = 0; q < 8; ++q) fma4(ag + 4*q, wk[q], g);
        }

        // residual: h_new = h_old + relu(skip)
        #pragma unroll
        for (int c = 0; c < CH; ++c) ag[c] = hr0[c] + fmaxf(ag[c], 0.0f);

        __syncthreads();   // everyone done reading old h
        #pragma unroll
        for (int c = 0; c < CH; ++c) hb[tid * HBSTRIDE + c] = in_seq ? ag[c] : 0.0f;
        // next iteration's leading __syncthreads() makes these writes visible
    }

    // ---- tail: skip_sum = h_final - h_init ; relu ; final 1x1 conv ; dense partial ----
    {
        const float4* g = (const float4*)w_final;
        float4* s = (float4*)swt;
        for (int j = tid; j < 256; j += NTHREADS) s[j] = g[j];
        if (tid < CH) {
            sbt[tid] = b_final[tid];
            sbs[tid] = w_init[tid];
            sbk[tid] = b_init[tid];
        }
    }
    __syncthreads();

    float l0 = 0.0f, l1 = 0.0f;
    const bool valid = (tid >= HALO) && (tid < HALO + T_TILE) && (tg < TLEN);
    if (valid) {
        float y1[CH];
        #pragma unroll
        for (int c = 0; c < CH; ++c) {
            float hinit = fmaxf(fmaf(xv, sbs[c], sbk[c]), 0.0f);
            float ss = hb[tid * HBSTRIDE + c] - hinit;   // skip_sum
            y1[c] = fmaxf(ss, 0.0f);                     // relu(skip_sum)
        }
        #pragma unroll
        for (int c = 0; c < CH; ++c) at[c] = sbt[c];
        #pragma unroll 1
        for (int ci = 0; ci < CH; ++ci) {
            const float g = y1[ci];
            const float4* wf = (const float4*)(swt + ci*CH);
            #pragma unroll
            for (int q = 0; q < 8; ++q) fma4(at + 4*q, wf[q], g);
        }
        const float2* wd = (const float2*)w_dense + (size_t)tg * CH;
        #pragma unroll
        for (int c = 0; c < CH; ++c) {
            float yv = fmaxf(at[c], 0.0f);               // relu(final conv)
            float2 w = __ldg(&wd[c]);
            l0 = fmaf(yv, w.x, l0);
            l1 = fmaf(yv, w.y, l1);
        }
    }

    // deterministic CTA reduction
    #pragma unroll
    for (int off = 16; off > 0; off >>= 1) {
        l0 += __shfl_down_sync(0xffffffffu, l0, off);
        l1 += __shfl_down_sync(0xffffffffu, l1, off);
    }
    const int wid = tid >> 5, lane = tid & 31;
    if (lane == 0) { sred[wid*2] = l0; sred[wid*2 + 1] = l1; }
    __syncthreads();
    if (tid == 0) {
        float s0 = 0.0f, s1 = 0.0f;
        #pragma unroll
        for (int w = 0; w < NWARPS; ++w) { s0 += sred[w*2]; s1 += sred[w*2 + 1]; }
        g_partials[(b * NTILES + tile) * 2 + 0] = s0;
        g_partials[(b * NTILES + tile) * 2 + 1] = s1;
    }
}

__global__ void finalize_kernel(const float* __restrict__ b_dense, float* __restrict__ out)
{
    int b = threadIdx.x;
    if (b < BATCH) {
        float s0 = b_dense[0], s1 = b_dense[1];
        for (int t = 0; t < NTILES; ++t) {
            s0 += g_partials[(b * NTILES + t) * 2 + 0];
            s1 += g_partials[(b * NTILES + t) * 2 + 1];
        }
        float m  = fmaxf(s0, s1);
        float e0 = expf(s0 - m), e1 = expf(s1 - m);
        float inv = 1.0f / (e0 + e1);
        out[b*2 + 0] = e0 * inv;
        out[b*2 + 1] = e1 * inv;
    }
}

extern "C" void kernel_launch(void* const* d_in, const int* in_sizes, int n_in,
                              void* d_out, int out_size)
{
    const float* x       = (const float*)d_in[0];
    const float* w_init  = (const float*)d_in[1];
    const float* b_init  = (const float*)d_in[2];
    const float* w_tanh  = (const float*)d_in[3];
    const float* b_tanh  = (const float*)d_in[4];
    const float* w_sig   = (const float*)d_in[5];
    const float* b_sig   = (const float*)d_in[6];
    const float* w_skip  = (const float*)d_in[7];
    const float* b_skip  = (const float*)d_in[8];
    const float* w_final = (const float*)d_in[9];
    const float* b_final = (const float*)d_in[10];
    const float* w_dense = (const float*)d_in[11];
    const float* b_dense = (const float*)d_in[12];

    cudaFuncSetAttribute(wavenet_kernel,
                         cudaFuncAttributeMaxDynamicSharedMemorySize, SMEM_BYTES);

    wavenet_kernel<<<BATCH * NTILES, NTHREADS, SMEM_BYTES>>>(
        x, w_init, b_init, w_tanh, b_tanh, w_sig, b_sig,
        w_skip, b_skip, w_final, b_final, w_dense);

    finalize_kernel<<<1, 32>>>(b_dense, (float*)d_out);
}